// round 5
// baseline (speedup 1.0000x reference)
#include <cuda_runtime.h>
#include <cuda_bf16.h>
#include <cstdint>

#define VOCAB 4
#define DIM   128
#define MAX_SEGS 8192
#define CHUNK 32               // tokens per chunk; chunk base is 128B-aligned
#define BLOCK 256
#define MAX_GRID 592           // 148 SMs x 4 blocks -> guaranteed co-resident

// Per-segment, per-vocab histogram. Zeroed at load; combine phase re-zeros
// after consuming -> invariant "all zero on entry" holds every launch/replay.
__device__ int g_counts[MAX_SEGS * VOCAB];
// Grid-barrier state. Reset to 0 by the last-finishing block each launch.
__device__ unsigned int g_bar;
__device__ unsigned int g_done;

// Recover n0..n3 from (n, ssum=Σt, s0=Σ(t&1), s3=Σ(t==3)) and flush.
__device__ __forceinline__ void flush_counts(int seg, int n, int ssum, int s0, int s3) {
    if (n == 0) return;
    int n3 = s3;
    int n1 = s0 - s3;
    int n2 = (ssum - s0 - 2 * s3) >> 1;
    int n0 = n - n1 - n2 - n3;
    int* base = &g_counts[seg * VOCAB];
    if (n0) atomicAdd(base + 0, n0);
    if (n1) atomicAdd(base + 1, n1);
    if (n2) atomicAdd(base + 2, n2);
    if (n3) atomicAdd(base + 3, n3);
}

__device__ __forceinline__ void do_chunk(const int* __restrict__ tokens,
                                         const int* __restrict__ segids,
                                         int T, long long base_ll) {
    int base = (int)base_ll;

    if (base_ll + CHUNK <= T) {
        int s_first = __ldg(&segids[base]);
        int s_last  = __ldg(&segids[base + CHUNK - 1]);
        if (s_first == s_last) {
            // fast path: whole chunk in one segment, branch-free dp4a count
            const int4* t4 = (const int4*)(tokens + base);
            int ssum = 0, s0 = 0, s3 = 0;
            #pragma unroll
            for (int k = 0; k < CHUNK / 4; k++) {
                int4 tk = __ldg(&t4[k]);
                unsigned a = __byte_perm((unsigned)tk.x, (unsigned)tk.y, 0x0040);
                unsigned b = __byte_perm((unsigned)tk.z, (unsigned)tk.w, 0x0040);
                unsigned p = __byte_perm(a, b, 0x5410);
                unsigned u  = p >> 1;
                unsigned b0 = p & 0x01010101u;
                unsigned b3 = p & u & 0x01010101u;
                ssum = __dp4a((int)p,  0x01010101, ssum);
                s0   = __dp4a((int)b0, 0x01010101, s0);
                s3   = __dp4a((int)b3, 0x01010101, s3);
            }
            flush_counts(s_first, CHUNK, ssum, s0, s3);
            return;
        }
    }

    // slow path: boundary chunk (or tail)
    int end = (int)min((long long)T, base_ll + CHUNK);
    int cur = __ldg(&segids[base]);
    int n = 0, ssum = 0, s0 = 0, s3 = 0;
    for (int i = base; i < end; i++) {
        int s = __ldg(&segids[i]);
        int t = __ldg(&tokens[i]);
        if (s != cur) {
            flush_counts(cur, n, ssum, s0, s3);
            n = 0; ssum = 0; s0 = 0; s3 = 0; cur = s;
        }
        n++;
        ssum += t;
        s0   += t & 1;
        s3   += (t == 3);
    }
    flush_counts(cur, n, ssum, s0, s3);
}

__global__ void __launch_bounds__(BLOCK, 4)
fused_kernel(const int* __restrict__ tokens,
             const int* __restrict__ segids,
             const float* __restrict__ emb,
             float* __restrict__ out,
             int T, int R, int nchunks) {
    const int tid     = threadIdx.x;
    const int gt      = blockIdx.x * BLOCK + tid;
    const int nthread = gridDim.x * BLOCK;

    // ---------------- Phase 1: histogram ----------------
    for (int c = gt; c < nchunks; c += nthread)
        do_chunk(tokens, segids, T, (long long)c * CHUNK);

    // ---------------- Grid barrier (all CTAs co-resident) ----------------
    __syncthreads();
    if (tid == 0) {
        __threadfence();                      // release hist atomics
        atomicAdd(&g_bar, 1u);
        while (*(volatile unsigned int*)&g_bar < gridDim.x)
            __nanosleep(32);
        __threadfence();                      // acquire
    }
    __syncthreads();

    // ---------------- Phase 2: combine ----------------
    // out[r][d] = (Σ_v cnt[r][v] * emb[v][d]) / max(Σ_v cnt[r][v], 1)
    // One float4 per element-index; 32 consecutive indices = one segment,
    // so seg is warp-uniform each iteration (nthread is a multiple of 32).
    const int total = R * 32;                 // float4 elements
    const float4* e = (const float4*)emb;
    for (int i = gt; i < total; i += nthread) {
        int seg  = i >> 5;
        int lane = i & 31;

        int4 c = *(const int4*)&g_counts[seg * VOCAB];
        float f0 = (float)c.x, f1 = (float)c.y, f2 = (float)c.z, f3 = (float)c.w;
        float inv = 1.0f / fmaxf(f0 + f1 + f2 + f3, 1.0f);

        float4 e0 = __ldg(&e[0 * 32 + lane]);
        float4 e1 = __ldg(&e[1 * 32 + lane]);
        float4 e2 = __ldg(&e[2 * 32 + lane]);
        float4 e3 = __ldg(&e[3 * 32 + lane]);

        float4 r;
        r.x = (f0 * e0.x + f1 * e1.x + f2 * e2.x + f3 * e3.x) * inv;
        r.y = (f0 * e0.y + f1 * e1.y + f2 * e2.y + f3 * e3.y) * inv;
        r.z = (f0 * e0.z + f1 * e1.z + f2 * e2.z + f3 * e3.z) * inv;
        r.w = (f0 * e0.w + f1 * e1.w + f2 * e2.w + f3 * e3.w) * inv;
        ((float4*)out)[i] = r;

        __syncwarp();
        if (lane == 0)                        // restore zero invariant
            *(int4*)&g_counts[seg * VOCAB] = make_int4(0, 0, 0, 0);
    }

    // ---------------- Epilogue: last block resets barrier state ----------------
    __syncthreads();
    if (tid == 0) {
        __threadfence();
        unsigned int t = atomicAdd(&g_done, 1u);
        if (t == gridDim.x - 1) {             // everyone is past both phases
            g_bar  = 0u;
            g_done = 0u;
            __threadfence();
        }
    }
}

extern "C" void kernel_launch(void* const* d_in, const int* in_sizes, int n_in,
                              void* d_out, int out_size) {
    const int* tokens = (const int*)d_in[0];
    const int* segids = (const int*)d_in[1];
    const float* emb  = (const float*)d_in[2];
    float* out        = (float*)d_out;

    int T = in_sizes[0];
    int R = out_size / DIM;

    int nchunks = (T + CHUNK - 1) / CHUNK;
    int grid = (nchunks + BLOCK - 1) / BLOCK;
    if (grid > MAX_GRID) grid = MAX_GRID;     // keep all CTAs co-resident
    if (grid < 1) grid = 1;

    fused_kernel<<<grid, BLOCK>>>(tokens, segids, emb, out, T, R, nchunks);
}